// round 8
// baseline (speedup 1.0000x reference)
#include <cuda_runtime.h>
#include <cuda_bf16.h>
#include <math.h>
#include <stdint.h>

#define NB   2
#define NT   2048
#define NMEL 100
#define ND   1024
#define NH   16
#define NDH  64
#define NWIN 512
#define NFF  4096
#define NCD  1024
#define NLAYER 6
#define LNEPS 1e-5f

// ---------------- scratch (device globals) ----------------
__device__ float g_h   [NB*NT*ND];
__device__ float g_qkv [NB*NT*3*ND];
__device__ float g_ta  [NB*NCD];
__device__ float g_tb  [NB*NCD];
__device__ float g_cond[NB*ND];
__device__ float g_ss  [NB*2*ND];
__device__ float g_rc  [NT*(NDH/2)];
__device__ float g_rs  [NT*(NDH/2)];

// split activations (bf16 hi/lo)
__device__ __nv_bfloat16 g_xh  [NB*NT*128];
__device__ __nv_bfloat16 g_xl  [NB*NT*128];
__device__ __nv_bfloat16 g_hn_h[NB*NT*ND];
__device__ __nv_bfloat16 g_hn_l[NB*NT*ND];
__device__ __nv_bfloat16 g_at_h[NB*NT*ND];
__device__ __nv_bfloat16 g_at_l[NB*NT*ND];
__device__ __nv_bfloat16 g_ff_h[NB*NT*NFF];
__device__ __nv_bfloat16 g_ff_l[NB*NT*NFF];

// converted weights: [N][Kpad] bf16 hi/lo
__device__ __nv_bfloat16 c_in_hi  [ND*128];
__device__ __nv_bfloat16 c_in_lo  [ND*128];
__device__ __nv_bfloat16 c_qkv_hi [NLAYER*3*ND*ND];
__device__ __nv_bfloat16 c_qkv_lo [NLAYER*3*ND*ND];
__device__ __nv_bfloat16 c_ao_hi  [NLAYER*ND*ND];
__device__ __nv_bfloat16 c_ao_lo  [NLAYER*ND*ND];
__device__ __nv_bfloat16 c_m1_hi  [NLAYER*NFF*ND];
__device__ __nv_bfloat16 c_m1_lo  [NLAYER*NFF*ND];
__device__ __nv_bfloat16 c_m2_hi  [NLAYER*ND*NFF];
__device__ __nv_bfloat16 c_m2_lo  [NLAYER*ND*NFF];
__device__ __nv_bfloat16 c_out_hi [256*ND];        // N padded 100->256 rows
__device__ __nv_bfloat16 c_out_lo [256*ND];

// ---------------- helpers ----------------
__device__ __forceinline__ uint32_t smem_u32(const void* p){
    uint32_t a;
    asm("{ .reg .u64 t; cvta.to.shared.u64 t, %1; cvt.u32.u64 %0, t; }" : "=r"(a) : "l"(p));
    return a;
}
#define LDSM4(d0,d1,d2,d3,addr) \
    asm volatile("ldmatrix.sync.aligned.m8n8.x4.shared.b16 {%0,%1,%2,%3}, [%4];" \
        : "=r"(d0),"=r"(d1),"=r"(d2),"=r"(d3) : "r"(addr))
#define MMA16816(c, a, b0, b1) \
    asm volatile("mma.sync.aligned.m16n8k16.row.col.f32.bf16.bf16.f32 " \
        "{%0,%1,%2,%3},{%4,%5,%6,%7},{%8,%9},{%0,%1,%2,%3};" \
        : "+f"((c)[0]),"+f"((c)[1]),"+f"((c)[2]),"+f"((c)[3]) \
        : "r"((a)[0]),"r"((a)[1]),"r"((a)[2]),"r"((a)[3]),"r"(b0),"r"(b1))
#define CP_ASYNC16(dst, src) \
    asm volatile("cp.async.cg.shared.global [%0], [%1], 16;" :: "r"(dst), "l"(src))

__device__ __forceinline__ void split2(float v, __nv_bfloat16& h, __nv_bfloat16& l){
    h = __float2bfloat16_rn(v);
    l = __float2bfloat16_rn(v - __bfloat162float(h));
}

// ---------------- weight convert: W[K,N] fp32 -> [N,Kpad] bf16 hi/lo ----------------
__global__ void k_wconv(const float* __restrict__ W, __nv_bfloat16* __restrict__ hi,
                        __nv_bfloat16* __restrict__ lo, int K, int N, int Kpad){
    __shared__ float t[32][33];
    int kb = blockIdx.y*32, nb = blockIdx.x*32;
    int x = threadIdx.x, y = threadIdx.y;   // 32 x 8
    #pragma unroll
    for (int i = 0; i < 32; i += 8){
        int k = kb + y + i, n = nb + x;
        t[y+i][x] = (k < K && n < N) ? W[(size_t)k*N + n] : 0.f;
    }
    __syncthreads();
    #pragma unroll
    for (int i = 0; i < 32; i += 8){
        int n = nb + y + i, k = kb + x;
        if (n < N && k < Kpad){
            float v = t[x][y+i];
            __nv_bfloat16 h, l; split2(v, h, l);
            hi[(size_t)n*Kpad + k] = h;
            lo[(size_t)n*Kpad + k] = l;
        }
    }
}

// ---------------- x split: [M][K] fp32 -> [M][128] bf16 hi/lo (zero pad) ----------------
__global__ void k_split(const float* __restrict__ X, __nv_bfloat16* __restrict__ Xh,
                        __nv_bfloat16* __restrict__ Xl){
    int i = blockIdx.x*blockDim.x + threadIdx.x;   // M*128
    int row = i >> 7, col = i & 127;
    float v = (col < NMEL) ? X[(size_t)row*NMEL + col] : 0.f;
    __nv_bfloat16 h, l; split2(v, h, l);
    Xh[i] = h; Xl[i] = l;
}

// ---------------- pipelined tensor-core GEMM v3 (bf16 hi/lo split, fp32 accum) ---------
// C = act(A @ B^T + bias) (+resid). CTA tile 128m x 256n, warp tile 64x64, BK=32.
#define AST 40
#define A_ELEM (128*AST)                 // 5120 halves
#define B_ELEM (256*AST)                 // 10240 halves
#define STAGE  (2*A_ELEM + 2*B_ELEM)     // 30720 halves = 61440 B
__global__ __launch_bounds__(256, 1) void k_mgemm(
    const __nv_bfloat16* __restrict__ Ahi, const __nv_bfloat16* __restrict__ Alo, int lda,
    const __nv_bfloat16* __restrict__ Bhi, const __nv_bfloat16* __restrict__ Blo,
    const float* __restrict__ bias, const float* __restrict__ resid,
    float* __restrict__ C, __nv_bfloat16* __restrict__ Chi, __nv_bfloat16* __restrict__ Clo,
    int N, int K, int act)
{
    extern __shared__ __nv_bfloat16 sm[];
    int tid = threadIdx.x, lane = tid & 31, w = tid >> 5;
    int m0 = blockIdx.y * 128, n0 = blockIdx.x * 256;
    int wm = (w & 1) * 64;
    int wn = (w >> 1) * 64;
    uint32_t sb = smem_u32(sm);

    float acc[32][4];
    #pragma unroll
    for (int i = 0; i < 32; i++){
        acc[i][0]=0.f; acc[i][1]=0.f; acc[i][2]=0.f; acc[i][3]=0.f;
    }

    int nchunks = K >> 5;

    // ---- prefetch: 3072 x 16B per chunk, 12 per thread ----
    #define PREFETCH(stage, k0) do {                                               \
        uint32_t s0 = sb + (stage)*(STAGE*2);                                      \
        _Pragma("unroll")                                                          \
        for (int j = 0; j < 12; j++){                                              \
            int i = tid + j*256;                                                   \
            if (i < 1024){                                                         \
                int half = i >> 9, idx = i & 511;                                  \
                int r = idx >> 2, ch = idx & 3;                                    \
                const __nv_bfloat16* gp = (half ? Alo : Ahi)                       \
                    + (size_t)(m0 + r)*lda + (k0) + ch*8;                          \
                uint32_t dst = s0 + half*(A_ELEM*2) + r*(AST*2) + ch*16;           \
                CP_ASYNC16(dst, gp);                                               \
            } else {                                                               \
                int ii = i - 1024;                                                 \
                int half = ii >> 10, idx = ii & 1023;                              \
                int r = idx >> 2, ch = idx & 3;                                    \
                const __nv_bfloat16* gp = (half ? Blo : Bhi)                       \
                    + (size_t)(n0 + r)*K + (k0) + ch*8;                            \
                uint32_t dst = s0 + 2*(A_ELEM*2) + half*(B_ELEM*2)                 \
                             + r*(AST*2) + ch*16;                                  \
                CP_ASYNC16(dst, gp);                                               \
            }                                                                      \
        }                                                                          \
    } while(0)

    PREFETCH(0, 0);
    asm volatile("cp.async.commit_group;" ::: "memory");

    for (int c = 0; c < nchunks; c++){
        if (c + 1 < nchunks){
            PREFETCH((c+1)&1, (c+1)*32);
            asm volatile("cp.async.commit_group;" ::: "memory");
            asm volatile("cp.async.wait_group 1;" ::: "memory");
        } else {
            asm volatile("cp.async.wait_group 0;" ::: "memory");
        }
        __syncthreads();

        __nv_bfloat16* st  = sm + (c&1)*STAGE;
        __nv_bfloat16* sAh = st;
        __nv_bfloat16* sAl = st + A_ELEM;
        __nv_bfloat16* sBh = st + 2*A_ELEM;
        __nv_bfloat16* sBl = st + 2*A_ELEM + B_ELEM;

        #pragma unroll
        for (int ks = 0; ks < 2; ks++){
            int kb = ks * 16 + (lane >> 4) * 8;
            int rr = lane & 15;
            uint32_t ah[4][4], al[4][4], bfr[4][4];
            #pragma unroll
            for (int mi = 0; mi < 4; mi++){
                uint32_t ad = smem_u32(&sAh[(wm + mi*16 + rr)*AST + kb]);
                LDSM4(ah[mi][0], ah[mi][1], ah[mi][2], ah[mi][3], ad);
            }
            #pragma unroll
            for (int mi = 0; mi < 4; mi++){
                uint32_t ad = smem_u32(&sAl[(wm + mi*16 + rr)*AST + kb]);
                LDSM4(al[mi][0], al[mi][1], al[mi][2], al[mi][3], ad);
            }
            #pragma unroll
            for (int nj = 0; nj < 4; nj++){
                uint32_t ad = smem_u32(&sBh[(wn + nj*16 + rr)*AST + kb]);
                LDSM4(bfr[nj][0], bfr[nj][1], bfr[nj][2], bfr[nj][3], ad);
            }
            #pragma unroll
            for (int mi = 0; mi < 4; mi++)
                #pragma unroll
                for (int ni = 0; ni < 8; ni++){
                    uint32_t b0 = bfr[ni>>1][(ni&1)];
                    uint32_t b1 = bfr[ni>>1][(ni&1)+2];
                    MMA16816(acc[mi*8+ni], ah[mi], b0, b1);   // hi*hi
                    MMA16816(acc[mi*8+ni], al[mi], b0, b1);   // lo*hi
                }
            #pragma unroll
            for (int nj = 0; nj < 4; nj++){
                uint32_t ad = smem_u32(&sBl[(wn + nj*16 + rr)*AST + kb]);
                LDSM4(bfr[nj][0], bfr[nj][1], bfr[nj][2], bfr[nj][3], ad);
            }
            #pragma unroll
            for (int mi = 0; mi < 4; mi++)
                #pragma unroll
                for (int ni = 0; ni < 8; ni++){
                    uint32_t b0 = bfr[ni>>1][(ni&1)];
                    uint32_t b1 = bfr[ni>>1][(ni&1)+2];
                    MMA16816(acc[mi*8+ni], ah[mi], b0, b1);   // hi*lo
                }
        }
        __syncthreads();
    }

    // ---- epilogue ----
    #pragma unroll
    for (int mi = 0; mi < 4; mi++){
        #pragma unroll
        for (int ni = 0; ni < 8; ni++){
            float* ac = acc[mi*8+ni];
            int n = n0 + wn + ni*8 + (lane & 3)*2;
            if (n + 1 < N){
                float b0 = bias[n], b1 = bias[n+1];
                #pragma unroll
                for (int half = 0; half < 2; half++){
                    int m = m0 + wm + mi*16 + (lane >> 2) + half*8;
                    float v0 = ac[half*2]   + b0;
                    float v1 = ac[half*2+1] + b1;
                    if (act == 1){
                        v0 = 0.5f*v0*(1.f + erff(v0*0.70710678118654752f));
                        v1 = 0.5f*v1*(1.f + erff(v1*0.70710678118654752f));
                    }
                    if (Chi){
                        __nv_bfloat16 h0,l0,h1,l1;
                        split2(v0,h0,l0); split2(v1,h1,l1);
                        __nv_bfloat162 hp, lp;
                        hp.x=h0; hp.y=h1; lp.x=l0; lp.y=l1;
                        *(__nv_bfloat162*)(Chi + (size_t)m*N + n) = hp;
                        *(__nv_bfloat162*)(Clo + (size_t)m*N + n) = lp;
                    } else {
                        if (resid){
                            float2 rp = *(const float2*)(resid + (size_t)m*N + n);
                            v0 += rp.x; v1 += rp.y;
                        }
                        float2 o = make_float2(v0, v1);
                        *(float2*)(C + (size_t)m*N + n) = o;
                    }
                }
            } else if (n < N){
                float b0 = bias[n];
                #pragma unroll
                for (int half = 0; half < 2; half++){
                    int m = m0 + wm + mi*16 + (lane >> 2) + half*8;
                    float v0 = ac[half*2] + b0;
                    if (act == 1) v0 = 0.5f*v0*(1.f + erff(v0*0.70710678118654752f));
                    if (Chi){
                        __nv_bfloat16 h0,l0; split2(v0,h0,l0);
                        Chi[(size_t)m*N + n] = h0;
                        Clo[(size_t)m*N + n] = l0;
                    } else {
                        if (resid) v0 += resid[(size_t)m*N + n];
                        C[(size_t)m*N + n] = v0;
                    }
                }
            }
        }
    }
    #undef PREFETCH
}

// ---------------- timestep embedding features ----------------
__global__ void k_tfeat(const float* __restrict__ t, float* __restrict__ out){
    int i = blockIdx.x*blockDim.x + threadIdx.x;
    if (i >= NB*NCD) return;
    int b = i / NCD, j = i % NCD;
    const int half = NCD/2;
    int idx = (j < half) ? j : (j - half);
    float f   = expf(-9.210340371976184f * (float)idx / (float)half);
    float ang = t[b] * f;
    out[i] = (j < half) ? sinf(ang) : cosf(ang);
}

// ---------------- small GEMM (rows = NB only), k-split parallel ----------------
__global__ __launch_bounds__(256) void k_sgemm2(const float* __restrict__ X,
                                                const float* __restrict__ W,
                                                const float* __restrict__ bias,
                                                float* __restrict__ Y,
                                                int K, int N, int act){
    __shared__ float red[2][4][65];
    int lane = threadIdx.x & 63;
    int slice = threadIdx.x >> 6;
    int n = blockIdx.x*64 + lane;
    int kps = K >> 2;
    float a0 = 0.f, a1 = 0.f;
    if (n < N){
        const float* x0 = X;
        const float* x1 = X + K;
        int k0 = slice*kps, k1 = k0 + kps;
        #pragma unroll 4
        for (int k = k0; k < k1; k++){
            float w = W[(size_t)k*N + n];
            a0 += x0[k]*w; a1 += x1[k]*w;
        }
    }
    red[0][slice][lane] = a0;
    red[1][slice][lane] = a1;
    __syncthreads();
    if (threadIdx.x < 128){
        int bb = threadIdx.x >> 6, l = threadIdx.x & 63;
        float s = red[bb][0][l] + red[bb][1][l] + red[bb][2][l] + red[bb][3][l];
        int nn = blockIdx.x*64 + l;
        if (nn < N){
            s += bias[nn];
            if (act == 1) s = s / (1.f + expf(-s));
            Y[(size_t)bb*N + nn] = s;
        }
    }
}

// ---------------- rope tables + apply ----------------
__global__ void k_rope_tab(){
    int i = blockIdx.x*blockDim.x + threadIdx.x;
    if (i >= NT*(NDH/2)) return;
    int t = i >> 5, j = i & 31;
    float freq = (float)pow(10000.0, -(double)(2*j) / (double)NDH);
    float ang  = (float)t * freq;
    g_rc[i] = cosf(ang);
    g_rs[i] = sinf(ang);
}
__global__ void k_rope(float* __restrict__ qkv){
    int i = blockIdx.x*blockDim.x + threadIdx.x;
    int j = i & 31;
    int h = (i >> 5) & 15;
    int c = (i >> 9) & 1;
    int t = (i >> 10) & (NT-1);
    int b = i >> 21;
    size_t base = (((size_t)(b*NT + t)*3 + c)*NH + h) * NDH;
    float x1 = qkv[base + 2*j], x2 = qkv[base + 2*j + 1];
    float cs = g_rc[t*32 + j], sn = g_rs[t*32 + j];
    qkv[base + 2*j]     = x1*cs - x2*sn;
    qkv[base + 2*j + 1] = x1*sn + x2*cs;
}

// ---------------- LayerNorm (+adaLN), split bf16 hi/lo output ----------------
__global__ __launch_bounds__(256) void k_ln(const float* __restrict__ X,
                                            const float* __restrict__ ss,
                                            __nv_bfloat16* __restrict__ Yh,
                                            __nv_bfloat16* __restrict__ Yl){
    int row = blockIdx.x;
    int b = row / NT;
    const float4* x4 = (const float4*)(X + (size_t)row*ND);
    int tid = threadIdx.x;
    float4 v = x4[tid];
    float s = v.x+v.y+v.z+v.w;
    float q = v.x*v.x+v.y*v.y+v.z*v.z+v.w*v.w;
    #pragma unroll
    for (int o=16;o;o>>=1){ s += __shfl_xor_sync(0xffffffffu,s,o); q += __shfl_xor_sync(0xffffffffu,q,o); }
    __shared__ float shs[8], shq[8];
    __shared__ float smean, srstd;
    int w = tid>>5;
    if ((tid&31)==0){ shs[w]=s; shq[w]=q; }
    __syncthreads();
    if (tid==0){
        float S=0.f,Q=0.f;
        #pragma unroll
        for (int k=0;k<8;k++){ S+=shs[k]; Q+=shq[k]; }
        float mean = S*(1.f/ND);
        float var  = Q*(1.f/ND) - mean*mean;
        smean = mean; srstd = rsqrtf(var + LNEPS);
    }
    __syncthreads();
    float mean = smean, r = srstd;
    int n0 = tid*4;
    float o[4];
    o[0]=(v.x-mean)*r; o[1]=(v.y-mean)*r; o[2]=(v.z-mean)*r; o[3]=(v.w-mean)*r;
    if (ss){
        const float* sc = ss + (size_t)b*2*ND;
        const float* sh = sc + ND;
        #pragma unroll
        for (int j=0;j<4;j++) o[j] = o[j]*(1.f+sc[n0+j]) + sh[n0+j];
    }
    __nv_bfloat16 hh[4], ll[4];
    #pragma unroll
    for (int j=0;j<4;j++) split2(o[j], hh[j], ll[j]);
    *(uint2*)(Yh + (size_t)row*ND + n0) = *(uint2*)hh;
    *(uint2*)(Yl + (size_t)row*ND + n0) = *(uint2*)ll;
}

// ---------------- flash-style windowed causal attention v2 ----------------
// q-tile 128, k-tile 64, 256 threads, microtile 8 rows x 4 cols.
// smem floats: Qs[128*65] | Ks[64*65] | Vs[64*64] | Ps[128*65]  = 99584 B
#define AQ_OFF 0
#define AK_OFF (128*65)
#define AV_OFF (128*65 + 64*65)
#define AP_OFF (128*65 + 64*65 + 64*64)
#define ATT_SMEM ((128*65 + 64*65 + 64*64 + 128*65)*4)
__global__ __launch_bounds__(256) void k_attn(const float* __restrict__ qkv,
                                              __nv_bfloat16* __restrict__ Oh,
                                              __nv_bfloat16* __restrict__ Ol){
    extern __shared__ float smf[];
    float* Qs = smf + AQ_OFF;
    float* Ks = smf + AK_OFF;
    float* Vs = smf + AV_OFF;
    float* Ps = smf + AP_OFF;
    int qt = blockIdx.x, h = blockIdx.y, b = blockIdx.z;
    int tid = threadIdx.x, ty = tid>>4, tx = tid&15;
    int q0 = qt*128;
    const float scale = 0.125f;

    #pragma unroll
    for (int rep=0;rep<8;rep++){
        int f = tid + rep*256;
        int r = f>>4, c4 = (f&15)*4;
        size_t g = (((size_t)(b*NT + q0 + r)*3 + 0)*NH + h)*NDH + c4;
        float4 v = *(const float4*)(qkv + g);
        Qs[r*65 + c4  ] = v.x*scale;
        Qs[r*65 + c4+1] = v.y*scale;
        Qs[r*65 + c4+2] = v.z*scale;
        Qs[r*65 + c4+3] = v.w*scale;
    }
    __syncthreads();

    float Oa[8][4];
    float mo[8], lo[8];
    #pragma unroll
    for (int a=0;a<8;a++){
        mo[a] = -1e30f; lo[a] = 0.f;
        #pragma unroll
        for (int c=0;c<4;c++) Oa[a][c]=0.f;
    }

    int ktiles = min(8, 2*qt+2);
    for (int jt=0; jt<ktiles; jt++){
        int j0 = jt*64;
        #pragma unroll
        for (int rep=0;rep<4;rep++){
            int f = tid + rep*256;
            int r = f>>4, c4 = (f&15)*4;
            int tok = NT - NWIN + j0 + r;
            size_t gk = (((size_t)(b*NT + tok)*3 + 1)*NH + h)*NDH + c4;
            float4 kv = *(const float4*)(qkv + gk);
            float4 vv = *(const float4*)(qkv + gk + (size_t)NH*NDH);
            Ks[r*65+c4  ]=kv.x; Ks[r*65+c4+1]=kv.y;
            Ks[r*65+c4+2]=kv.z; Ks[r*65+c4+3]=kv.w;
            *(float4*)(Vs + r*64 + c4) = vv;
        }
        __syncthreads();

        float S[8][4];
        #pragma unroll
        for (int a=0;a<8;a++)
            #pragma unroll
            for (int bb=0;bb<4;bb++) S[a][bb]=0.f;
        for (int d=0; d<64; d++){
            float qa[8], kb[4];
            #pragma unroll
            for (int a=0;a<8;a++)  qa[a] = Qs[(ty*8+a)*65 + d];
            #pragma unroll
            for (int bb=0;bb<4;bb++) kb[bb] = Ks[(tx+16*bb)*65 + d];
            #pragma unroll
            for (int a=0;a<8;a++)
                #pragma unroll
                for (int bb=0;bb<4;bb++) S[a][bb] += qa[a]*kb[bb];
        }
        if (qt < 4 && jt >= 2*qt){   // diagonal-straddling tiles
            #pragma unroll
            for (int a=0;a<8;a++)
                #pragma unroll
                for (int bb=0;bb<4;bb++)
                    if (jt*64 + tx+16*bb > qt*128 + ty*8+a) S[a][bb] = -1e30f;
        }

        #pragma unroll
        for (int a=0;a<8;a++){
            float mx = fmaxf(fmaxf(S[a][0],S[a][1]), fmaxf(S[a][2],S[a][3]));
            mx = fmaxf(mx, __shfl_xor_sync(0xffffffffu, mx, 8));
            mx = fmaxf(mx, __shfl_xor_sync(0xffffffffu, mx, 4));
            mx = fmaxf(mx, __shfl_xor_sync(0xffffffffu, mx, 2));
            mx = fmaxf(mx, __shfl_xor_sync(0xffffffffu, mx, 1));
            float mn = fmaxf(mo[a], mx);
            float ls = 0.f;
            #pragma unroll
            for (int bb=0;bb<4;bb++){ S[a][bb] = expf(S[a][bb]-mn); ls += S[a][bb]; }
            ls += __shfl_xor_sync(0xffffffffu, ls, 8);
            ls += __shfl_xor_sync(0xffffffffu, ls, 4);
            ls += __shfl_xor_sync(0xffffffffu, ls, 2);
            ls += __shfl_xor_sync(0xffffffffu, ls, 1);
            float alpha = expf(mo[a]-mn);
            lo[a] = lo[a]*alpha + ls;
            mo[a] = mn;
            #pragma unroll
            for (int c=0;c<4;c++) Oa[a][c] *= alpha;
        }
        #pragma unroll
        for (int a=0;a<8;a++)
            #pragma unroll
            for (int bb=0;bb<4;bb++)
                Ps[(ty*8+a)*65 + tx+16*bb] = S[a][bb];
        __syncthreads();
        for (int jj=0;jj<64;jj++){
            float pa[8], vc[4];
            #pragma unroll
            for (int a=0;a<8;a++) pa[a] = Ps[(ty*8+a)*65 + jj];
            #pragma unroll
            for (int c=0;c<4;c++) vc[c] = Vs[jj*64 + tx+16*c];
            #pragma unroll
            for (int a=0;a<8;a++)
                #pragma unroll
                for (int c=0;c<4;c++) Oa[a][c] += pa[a]*vc[c];
        }
        __syncthreads();
    }
    #pragma unroll
    for (int a=0;a<8;a++){
        int qq = q0 + ty*8 + a;
        float inv = 1.f/lo[a];
        #pragma unroll
        for (int c=0;c<4;c++){
            float v = Oa[a][c]*inv;
            __nv_bfloat16 hh, ll; split2(v, hh, ll);
            size_t idx = (((size_t)(b*NT+qq))*NH + h)*NDH + tx + 16*c;
            Oh[idx] = hh; Ol[idx] = ll;
        }
    }
}

// ---------------- orchestration ----------------
extern "C" void kernel_launch(void* const* d_in, const int* in_sizes, int n_in,
                              void* d_out, int out_size){
    (void)in_sizes; (void)n_in; (void)out_size;
    const float* x      = (const float*)d_in[0];
    const float* t      = (const float*)d_in[1];
    const float* W_in   = (const float*)d_in[2];
    const float* b_in   = (const float*)d_in[3];
    const float* Wt1    = (const float*)d_in[4];
    const float* bt1    = (const float*)d_in[5];
    const float* Wt2    = (const float*)d_in[6];
    const float* bt2    = (const float*)d_in[7];
    const float* Wcm    = (const float*)d_in[8];
    const float* bcm    = (const float*)d_in[9];
    const float* ada1_W = (const float*)d_in[10];
    const float* ada1_b = (const float*)d_in[11];
    const float* qkv_W  = (const float*)d_in[12];
    const float* qkv_b  = (const float*)d_in[13];
    const float* attno_W= (const float*)d_in[14];
    const float* attno_b= (const float*)d_in[15];
    const float* ada2_W = (const float*)d_in[16];
    const float* ada2_b = (const float*)d_in[17];
    const float* mlp_W1 = (const float*)d_in[18];
    const float* mlp_b1 = (const float*)d_in[19];
    const float* mlp_W2 = (const float*)d_in[20];
    const float* mlp_b2 = (const float*)d_in[21];
    const float* W_out  = (const float*)d_in[22];
    const float* b_out  = (const float*)d_in[23];

    float *p_h,*p_qkv,*p_ta,*p_tb,*p_cond,*p_ss;
    cudaGetSymbolAddress((void**)&p_h,    g_h);
    cudaGetSymbolAddress((void**)&p_qkv,  g_qkv);
    cudaGetSymbolAddress((void**)&p_ta,   g_ta);
    cudaGetSymbolAddress((void**)&p_tb,   g_tb);
    cudaGetSymbolAddress((void**)&p_cond, g_cond);
    cudaGetSymbolAddress((void**)&p_ss,   g_ss);

    __nv_bfloat16 *p_xh,*p_xl,*p_hnh,*p_hnl,*p_ath,*p_atl,*p_ffh,*p_ffl;
    cudaGetSymbolAddress((void**)&p_xh,  g_xh);
    cudaGetSymbolAddress((void**)&p_xl,  g_xl);
    cudaGetSymbolAddress((void**)&p_hnh, g_hn_h);
    cudaGetSymbolAddress((void**)&p_hnl, g_hn_l);
    cudaGetSymbolAddress((void**)&p_ath, g_at_h);
    cudaGetSymbolAddress((void**)&p_atl, g_at_l);
    cudaGetSymbolAddress((void**)&p_ffh, g_ff_h);
    cudaGetSymbolAddress((void**)&p_ffl, g_ff_l);

    __nv_bfloat16 *w_in_h,*w_in_l,*w_qkv_h,*w_qkv_l,*w_ao_h,*w_ao_l;
    __nv_bfloat16 *w_m1_h,*w_m1_l,*w_m2_h,*w_m2_l,*w_out_h,*w_out_l;
    cudaGetSymbolAddress((void**)&w_in_h,  c_in_hi);
    cudaGetSymbolAddress((void**)&w_in_l,  c_in_lo);
    cudaGetSymbolAddress((void**)&w_qkv_h, c_qkv_hi);
    cudaGetSymbolAddress((void**)&w_qkv_l, c_qkv_lo);
    cudaGetSymbolAddress((void**)&w_ao_h,  c_ao_hi);
    cudaGetSymbolAddress((void**)&w_ao_l,  c_ao_lo);
    cudaGetSymbolAddress((void**)&w_m1_h,  c_m1_hi);
    cudaGetSymbolAddress((void**)&w_m1_l,  c_m1_lo);
    cudaGetSymbolAddress((void**)&w_m2_h,  c_m2_hi);
    cudaGetSymbolAddress((void**)&w_m2_l,  c_m2_lo);
    cudaGetSymbolAddress((void**)&w_out_h, c_out_hi);
    cudaGetSymbolAddress((void**)&w_out_l, c_out_lo);

    cudaFuncSetAttribute(k_attn,  cudaFuncAttributeMaxDynamicSharedMemorySize, ATT_SMEM);
    cudaFuncSetAttribute(k_mgemm, cudaFuncAttributeMaxDynamicSharedMemorySize, STAGE*2*2);

    const int M = NB*NT;
    const int MG_SMEM = STAGE*2*2;   // 122880
    dim3 wblk(32, 8);

    // ---- weight conversion ----
    k_wconv<<<dim3(ND/32, 128/32), wblk>>>(W_in,  w_in_h,  w_in_l,  NMEL, ND, 128);
    k_wconv<<<dim3((NMEL+31)/32, ND/32), wblk>>>(W_out, w_out_h, w_out_l, ND, NMEL, ND);
    for (int l = 0; l < NLAYER; l++){
        k_wconv<<<dim3(3*ND/32, ND/32), wblk>>>(qkv_W  + (size_t)l*ND*3*ND, w_qkv_h + (size_t)l*3*ND*ND, w_qkv_l + (size_t)l*3*ND*ND, ND, 3*ND, ND);
        k_wconv<<<dim3(ND/32,   ND/32), wblk>>>(attno_W+ (size_t)l*ND*ND,   w_ao_h  + (size_t)l*ND*ND,   w_ao_l  + (size_t)l*ND*ND,   ND, ND, ND);
        k_wconv<<<dim3(NFF/32,  ND/32), wblk>>>(mlp_W1 + (size_t)l*ND*NFF,  w_m1_h  + (size_t)l*NFF*ND,  w_m1_l  + (size_t)l*NFF*ND,  ND, NFF, ND);
        k_wconv<<<dim3(ND/32,  NFF/32), wblk>>>(mlp_W2 + (size_t)l*NFF*ND,  w_m2_h  + (size_t)l*ND*NFF,  w_m2_l  + (size_t)l*ND*NFF,  NFF, ND, NFF);
    }

    // ---- timestep conditioning ----
    k_tfeat<<<(NB*NCD+255)/256,256>>>(t, p_ta);
    k_sgemm2<<<NCD/64,256>>>(p_ta, Wt1, bt1, p_tb, NCD, NCD, 1);
    k_sgemm2<<<NCD/64,256>>>(p_tb, Wt2, bt2, p_ta, NCD, NCD, 0);
    k_sgemm2<<<ND/64, 256>>>(p_ta, Wcm, bcm, p_cond, NCD, ND, 1);
    k_rope_tab<<<(NT*32+255)/256,256>>>();

    // ---- input projection (padded K = 128) ----
    k_split<<<(M*128)/256, 256>>>(x, p_xh, p_xl);
    k_mgemm<<<dim3(4, 32), 256, MG_SMEM>>>(p_xh, p_xl, 128, w_in_h, w_in_l,
                                           b_in, nullptr, p_h, nullptr, nullptr,
                                           ND, 128, 0);

    for (int l = 0; l < NLAYER; l++){
        k_sgemm2<<<2*ND/64,256>>>(p_cond, ada1_W + (size_t)l*ND*2*ND,
                                  ada1_b + (size_t)l*2*ND, p_ss, ND, 2*ND, 0);
        k_ln<<<M,256>>>(p_h, p_ss, p_hnh, p_hnl);
        k_mgemm<<<dim3(12, 32), 256, MG_SMEM>>>(p_hnh, p_hnl, ND,
                                                w_qkv_h + (size_t)l*3*ND*ND,
                                                w_qkv_l + (size_t)l*3*ND*ND,
                                                qkv_b + (size_t)l*3*ND, nullptr,
                                                p_qkv, nullptr, nullptr,
                                                3*ND, ND, 0);
        k_rope<<<(1<<22)/256,256>>>(p_qkv);
        k_attn<<<dim3(NT/128, NH, NB), 256, ATT_SMEM>>>(p_qkv, p_ath, p_atl);
        k_mgemm<<<dim3(4, 32), 256, MG_SMEM>>>(p_ath, p_atl, ND,
                                               w_ao_h + (size_t)l*ND*ND,
                                               w_ao_l + (size_t)l*ND*ND,
                                               attno_b + (size_t)l*ND, p_h,
                                               p_h, nullptr, nullptr,
                                               ND, ND, 0);
        k_sgemm2<<<2*ND/64,256>>>(p_cond, ada2_W + (size_t)l*ND*2*ND,
                                  ada2_b + (size_t)l*2*ND, p_ss, ND, 2*ND, 0);
        k_ln<<<M,256>>>(p_h, p_ss, p_hnh, p_hnl);
        k_mgemm<<<dim3(16, 32), 256, MG_SMEM>>>(p_hnh, p_hnl, ND,
                                                w_m1_h + (size_t)l*NFF*ND,
                                                w_m1_l + (size_t)l*NFF*ND,
                                                mlp_b1 + (size_t)l*NFF, nullptr,
                                                nullptr, p_ffh, p_ffl,
                                                NFF, ND, 1);
        k_mgemm<<<dim3(4, 32), 256, MG_SMEM>>>(p_ffh, p_ffl, NFF,
                                               w_m2_h + (size_t)l*ND*NFF,
                                               w_m2_l + (size_t)l*ND*NFF,
                                               mlp_b2 + (size_t)l*ND, p_h,
                                               p_h, nullptr, nullptr,
                                               ND, NFF, 0);
    }

    k_ln<<<M,256>>>(p_h, nullptr, p_hnh, p_hnl);
    k_mgemm<<<dim3(1, 32), 256, MG_SMEM>>>(p_hnh, p_hnl, ND, w_out_h, w_out_l,
                                           b_out, nullptr, (float*)d_out,
                                           nullptr, nullptr, NMEL, ND, 0);
}

// round 9
// speedup vs baseline: 2.0317x; 2.0317x over previous
#include <cuda_runtime.h>
#include <cuda_bf16.h>
#include <math.h>
#include <stdint.h>

#define NB   2
#define NT   2048
#define NMEL 100
#define ND   1024
#define NH   16
#define NDH  64
#define NWIN 512
#define NFF  4096
#define NCD  1024
#define NLAYER 6
#define LNEPS 1e-5f

// ---------------- scratch (device globals) ----------------
__device__ float g_h   [NB*NT*ND];
__device__ float g_qkv [NB*NT*3*ND];
__device__ float g_ta  [NB*NCD];
__device__ float g_tb  [NB*NCD];
__device__ float g_cond[NB*ND];
__device__ float g_ss  [NB*2*ND];
__device__ float g_rc  [NT*(NDH/2)];
__device__ float g_rs  [NT*(NDH/2)];

// split activations (bf16 hi/lo)
__device__ __nv_bfloat16 g_xh  [NB*NT*128];
__device__ __nv_bfloat16 g_xl  [NB*NT*128];
__device__ __nv_bfloat16 g_hn_h[NB*NT*ND];
__device__ __nv_bfloat16 g_hn_l[NB*NT*ND];
__device__ __nv_bfloat16 g_at_h[NB*NT*ND];
__device__ __nv_bfloat16 g_at_l[NB*NT*ND];
__device__ __nv_bfloat16 g_ff_h[NB*NT*NFF];
__device__ __nv_bfloat16 g_ff_l[NB*NT*NFF];

// converted weights: [N][Kpad] bf16 hi/lo (N padded to 256-multiples where needed)
__device__ __nv_bfloat16 c_in_hi  [ND*128];
__device__ __nv_bfloat16 c_in_lo  [ND*128];
__device__ __nv_bfloat16 c_qkv_hi [NLAYER*3*ND*ND];
__device__ __nv_bfloat16 c_qkv_lo [NLAYER*3*ND*ND];
__device__ __nv_bfloat16 c_ao_hi  [NLAYER*ND*ND];
__device__ __nv_bfloat16 c_ao_lo  [NLAYER*ND*ND];
__device__ __nv_bfloat16 c_m1_hi  [NLAYER*NFF*ND];
__device__ __nv_bfloat16 c_m1_lo  [NLAYER*NFF*ND];
__device__ __nv_bfloat16 c_m2_hi  [NLAYER*ND*NFF];
__device__ __nv_bfloat16 c_m2_lo  [NLAYER*ND*NFF];
__device__ __nv_bfloat16 c_out_hi [256*ND];        // rows zero beyond 100
__device__ __nv_bfloat16 c_out_lo [256*ND];

// ---------------- helpers ----------------
__device__ __forceinline__ uint32_t smem_u32(const void* p){
    uint32_t a;
    asm("{ .reg .u64 t; cvta.to.shared.u64 t, %1; cvt.u32.u64 %0, t; }" : "=r"(a) : "l"(p));
    return a;
}
#define LDSM4(d0,d1,d2,d3,addr) \
    asm volatile("ldmatrix.sync.aligned.m8n8.x4.shared.b16 {%0,%1,%2,%3}, [%4];" \
        : "=r"(d0),"=r"(d1),"=r"(d2),"=r"(d3) : "r"(addr))
#define MMA16816(c, a, b0, b1) \
    asm volatile("mma.sync.aligned.m16n8k16.row.col.f32.bf16.bf16.f32 " \
        "{%0,%1,%2,%3},{%4,%5,%6,%7},{%8,%9},{%0,%1,%2,%3};" \
        : "+f"((c)[0]),"+f"((c)[1]),"+f"((c)[2]),"+f"((c)[3]) \
        : "r"((a)[0]),"r"((a)[1]),"r"((a)[2]),"r"((a)[3]),"r"(b0),"r"(b1))
#define CP_ASYNC16(dst, src) \
    asm volatile("cp.async.cg.shared.global [%0], [%1], 16;" :: "r"(dst), "l"(src))
#define CP_COMMIT() asm volatile("cp.async.commit_group;" ::: "memory")
#define CP_WAIT(n)  asm volatile("cp.async.wait_group %0;" :: "n"(n) : "memory")

__device__ __forceinline__ void split2(float v, __nv_bfloat16& h, __nv_bfloat16& l){
    h = __float2bfloat16_rn(v);
    l = __float2bfloat16_rn(v - __bfloat162float(h));
}
__device__ __forceinline__ uint32_t sw128(uint32_t off){ return off ^ ((off >> 3) & 0x70); }
__device__ __forceinline__ uint64_t smem_desc(uint32_t addr){
    uint64_t d = ((uint64_t)2u << 61) | ((uint64_t)1u << 46) |
                 ((uint64_t)64u << 32) | ((uint64_t)1u << 16);
    return d | (uint64_t)((addr >> 4) & 0x3FFF);
}
#define MBAR_INIT(addr, cnt) \
    asm volatile("mbarrier.init.shared.b64 [%0], %1;" :: "r"(addr), "r"(cnt) : "memory")
#define FENCE_ASYNC() asm volatile("fence.proxy.async.shared::cta;" ::: "memory")

#define TG_IDESC ((1u<<4) | (1u<<7) | (1u<<10) | (32u<<17) | (8u<<24))   // f32 acc, bf16, N=256, M=128

// ---------------- weight convert: W[K,N] fp32 -> [N,Kpad] bf16 hi/lo ----------------
__global__ void k_wconv(const float* __restrict__ W, __nv_bfloat16* __restrict__ hi,
                        __nv_bfloat16* __restrict__ lo, int K, int N, int Kpad){
    __shared__ float t[32][33];
    int kb = blockIdx.y*32, nb = blockIdx.x*32;
    int x = threadIdx.x, y = threadIdx.y;
    #pragma unroll
    for (int i = 0; i < 32; i += 8){
        int k = kb + y + i, n = nb + x;
        t[y+i][x] = (k < K && n < N) ? W[(size_t)k*N + n] : 0.f;
    }
    __syncthreads();
    #pragma unroll
    for (int i = 0; i < 32; i += 8){
        int n = nb + y + i, k = kb + x;
        if (n < N && k < Kpad){
            float v = t[x][y+i];
            __nv_bfloat16 h, l; split2(v, h, l);
            hi[(size_t)n*Kpad + k] = h;
            lo[(size_t)n*Kpad + k] = l;
        }
    }
}

// ---------------- x split ----------------
__global__ void k_split(const float* __restrict__ X, __nv_bfloat16* __restrict__ Xh,
                        __nv_bfloat16* __restrict__ Xl){
    int i = blockIdx.x*blockDim.x + threadIdx.x;
    int row = i >> 7, col = i & 127;
    float v = (col < NMEL) ? X[(size_t)row*NMEL + col] : 0.f;
    __nv_bfloat16 h, l; split2(v, h, l);
    Xh[i] = h; Xl[i] = l;
}

// ================= main GEMM: tile 128m x 256n, bf16 hi/lo 3-way split, fp32 accum ====
// tcgen05 path on sm_103a, mma.sync fallback elsewhere (satisfies compute_103 ptxas).
#define TG_SMEM 197632
__global__ __launch_bounds__(256, 1) __cluster_dims__(1,1,1) void k_tgemm(
    const __nv_bfloat16* __restrict__ Ahi, const __nv_bfloat16* __restrict__ Alo, int lda,
    const __nv_bfloat16* __restrict__ Bhi, const __nv_bfloat16* __restrict__ Blo,
    const float* __restrict__ bias, const float* __restrict__ resid,
    float* __restrict__ C, __nv_bfloat16* __restrict__ Chi, __nv_bfloat16* __restrict__ Clo,
    int N, int K, int act)
{
    extern __shared__ char dyn[];
    int tid = threadIdx.x, lane = tid & 31, wid = tid >> 5;
    int m0 = blockIdx.x * 128;
    int nbase = blockIdx.y * 256;

#if defined(__CUDA_ARCH__) && defined(__CUDA_ARCH_FEAT_SM103_ALL)
    // ---------------- tcgen05 path ----------------
    __shared__ uint64_t s_mbar[2];
    __shared__ uint32_t s_tmem[1];
    uint32_t sbase = (smem_u32(dyn) + 1023u) & ~1023u;
    char* smp = dyn + (sbase - smem_u32(dyn));
    const uint32_t STG = 98304;              // 96KB per stage

    if (tid == 0){
        MBAR_INIT(smem_u32(&s_mbar[0]), 1);
        MBAR_INIT(smem_u32(&s_mbar[1]), 1);
    }
    if (wid == 0){
        asm volatile("tcgen05.alloc.cta_group::1.sync.aligned.shared::cta.b32 [%0], 256;"
                     :: "r"(smem_u32(s_tmem)) : "memory");
        asm volatile("tcgen05.relinquish_alloc_permit.cta_group::1.sync.aligned;");
    }
    __syncthreads();
    uint32_t tmem = s_tmem[0];
    uint32_t mb[2] = { smem_u32(&s_mbar[0]), smem_u32(&s_mbar[1]) };

    int nch = K >> 6;
    // per chunk: A hi/lo 128 rows x 128B @ 0/16K, B hi/lo 256 rows x 128B @ 32K/64K
    #define TGLOAD(stage, k0) do {                                                 \
        uint32_t s0 = sbase + (stage)*STG;                                         \
        _Pragma("unroll")                                                          \
        for (int j = 0; j < 24; j++){                                              \
            int i = tid + j*256;                                                   \
            uint32_t dst; const __nv_bfloat16* gp;                                 \
            if (i < 2048){                                                         \
                int half = i >> 10, idx = i & 1023;                                \
                int r = idx >> 3, ch = idx & 7;                                    \
                gp = (half ? Alo : Ahi) + (size_t)(m0 + r)*lda + (k0) + ch*8;      \
                dst = s0 + half*16384u + sw128((uint32_t)(r*128 + ch*16));         \
            } else {                                                               \
                int ii = i - 2048;                                                 \
                int half = ii >> 11, idx = ii & 2047;                              \
                int r = idx >> 3, ch = idx & 7;                                    \
                gp = (half ? Blo : Bhi) + (size_t)(nbase + r)*K + (k0) + ch*8;     \
                dst = s0 + 32768u + half*32768u + sw128((uint32_t)(r*128 + ch*16));\
            }                                                                      \
            CP_ASYNC16(dst, gp);                                                   \
        }                                                                          \
    } while(0)

    TGLOAD(0, 0);
    CP_COMMIT();
    uint32_t ph[2] = {0u, 0u};

    for (int c = 0; c < nch; c++){
        if (c + 1 < nch){
            int s2 = (c+1) & 1;
            if (c >= 1){
                // stage s2 last used by MMA of chunk c-1: wait for its commit
                asm volatile("{\n\t.reg .pred P;\n\tWL_%=:\n\t"
                    "mbarrier.try_wait.parity.acquire.cta.shared::cta.b64 P, [%0], %1, 0x989680;\n\t"
                    "@P bra.uni WD_%=;\n\tbra.uni WL_%=;\n\tWD_%=:\n\t}"
                    :: "r"(mb[s2]), "r"(ph[s2]) : "memory");
                ph[s2] ^= 1u;
            }
            TGLOAD(s2, (c+1)*64);
            CP_COMMIT();
            CP_WAIT(1);
        } else {
            CP_WAIT(0);
        }
        __syncthreads();
        FENCE_ASYNC();
        if (wid == 0){
            uint32_t pe;
            asm volatile("{\n\t.reg .pred p;\n\telect.sync _|p, 0xFFFFFFFF;\n\tselp.b32 %0, 1, 0, p;\n\t}" : "=r"(pe));
            if (pe){
                uint32_t base = sbase + (c&1)*STG;
                uint64_t ah = smem_desc(base);
                uint64_t al = smem_desc(base + 16384u);
                uint64_t bh = smem_desc(base + 32768u);
                uint64_t bl = smem_desc(base + 65536u);
                #pragma unroll
                for (int ks = 0; ks < 4; ks++){
                    uint32_t a0 = (c > 0 || ks > 0) ? 1u : 0u;
                    asm volatile("{\n\t.reg .pred p;\n\tsetp.ne.u32 p, %5, 0;\n\t"
                        "tcgen05.mma.cta_group::1.kind::f16 [%0], %1, %2, %3, {%4,%4,%4,%4}, p;\n\t}"
                        :: "r"(tmem), "l"(ah + ks*2), "l"(bh + ks*2), "r"(TG_IDESC), "r"(0u), "r"(a0) : "memory");
                    asm volatile("{\n\t.reg .pred p;\n\tsetp.ne.u32 p, %5, 0;\n\t"
                        "tcgen05.mma.cta_group::1.kind::f16 [%0], %1, %2, %3, {%4,%4,%4,%4}, p;\n\t}"
                        :: "r"(tmem), "l"(al + ks*2), "l"(bh + ks*2), "r"(TG_IDESC), "r"(0u), "r"(1u) : "memory");
                    asm volatile("{\n\t.reg .pred p;\n\tsetp.ne.u32 p, %5, 0;\n\t"
                        "tcgen05.mma.cta_group::1.kind::f16 [%0], %1, %2, %3, {%4,%4,%4,%4}, p;\n\t}"
                        :: "r"(tmem), "l"(ah + ks*2), "l"(bl + ks*2), "r"(TG_IDESC), "r"(0u), "r"(1u) : "memory");
                }
                asm volatile("tcgen05.commit.cta_group::1.mbarrier::arrive::one.shared::cluster.b64 [%0];"
                             :: "r"(mb[c&1]) : "memory");
            }
        }
    }
    // final MMA wait
    {
        int s = (nch-1) & 1;
        asm volatile("{\n\t.reg .pred P;\n\tWL_%=:\n\t"
            "mbarrier.try_wait.parity.acquire.cta.shared::cta.b64 P, [%0], %1, 0x989680;\n\t"
            "@P bra.uni WD_%=;\n\tbra.uni WL_%=;\n\tWD_%=:\n\t}"
            :: "r"(mb[s]), "r"(ph[s]) : "memory");
    }
    asm volatile("tcgen05.fence::after_thread_sync;" ::: "memory");

    // epilogue: TMEM -> smem staging (stride 261) -> fused stores
    float* stg = (float*)smp;
    int cb = (wid >> 2) * 128;
    int row = (wid & 3) * 32 + lane;
    #pragma unroll
    for (int r = 0; r < 4; r++){
        uint32_t dreg[32];
        asm volatile("tcgen05.ld.sync.aligned.32x32b.x32.b32 "
            "{%0,%1,%2,%3,%4,%5,%6,%7,%8,%9,%10,%11,%12,%13,%14,%15,"
            "%16,%17,%18,%19,%20,%21,%22,%23,%24,%25,%26,%27,%28,%29,%30,%31}, [%32];"
            : "=r"(dreg[0]),"=r"(dreg[1]),"=r"(dreg[2]),"=r"(dreg[3]),"=r"(dreg[4]),"=r"(dreg[5]),"=r"(dreg[6]),"=r"(dreg[7]),
              "=r"(dreg[8]),"=r"(dreg[9]),"=r"(dreg[10]),"=r"(dreg[11]),"=r"(dreg[12]),"=r"(dreg[13]),"=r"(dreg[14]),"=r"(dreg[15]),
              "=r"(dreg[16]),"=r"(dreg[17]),"=r"(dreg[18]),"=r"(dreg[19]),"=r"(dreg[20]),"=r"(dreg[21]),"=r"(dreg[22]),"=r"(dreg[23]),
              "=r"(dreg[24]),"=r"(dreg[25]),"=r"(dreg[26]),"=r"(dreg[27]),"=r"(dreg[28]),"=r"(dreg[29]),"=r"(dreg[30]),"=r"(dreg[31])
            : "r"(tmem + cb + r*32));
        asm volatile("tcgen05.wait::ld.sync.aligned;" ::: "memory");
        #pragma unroll
        for (int j = 0; j < 32; j++)
            stg[row*261 + cb + r*32 + j] = __uint_as_float(dreg[j]);
    }
    __syncthreads();
    if (wid == 0)
        asm volatile("tcgen05.dealloc.cta_group::1.sync.aligned.b32 %0, 256;" :: "r"(tmem));

    for (int i = tid; i < 8192; i += 256){
        int r = i >> 6, q = (i & 63) * 4;
        int m = m0 + r, n = nbase + q;
        if (n + 3 < N){
            float v0 = stg[r*261 + q]     + bias[n];
            float v1 = stg[r*261 + q + 1] + bias[n+1];
            float v2 = stg[r*261 + q + 2] + bias[n+2];
            float v3 = stg[r*261 + q + 3] + bias[n+3];
            if (act == 1){
                v0 = 0.5f*v0*(1.f + erff(v0*0.70710678118654752f));
                v1 = 0.5f*v1*(1.f + erff(v1*0.70710678118654752f));
                v2 = 0.5f*v2*(1.f + erff(v2*0.70710678118654752f));
                v3 = 0.5f*v3*(1.f + erff(v3*0.70710678118654752f));
            }
            if (Chi){
                __nv_bfloat16 h0,l0,h1,l1,h2,l2,h3,l3;
                split2(v0,h0,l0); split2(v1,h1,l1); split2(v2,h2,l2); split2(v3,h3,l3);
                __nv_bfloat162 hp0; hp0.x=h0; hp0.y=h1;
                __nv_bfloat162 hp1; hp1.x=h2; hp1.y=h3;
                __nv_bfloat162 lp0; lp0.x=l0; lp0.y=l1;
                __nv_bfloat162 lp1; lp1.x=l2; lp1.y=l3;
                *(__nv_bfloat162*)(Chi + (size_t)m*N + n)     = hp0;
                *(__nv_bfloat162*)(Chi + (size_t)m*N + n + 2) = hp1;
                *(__nv_bfloat162*)(Clo + (size_t)m*N + n)     = lp0;
                *(__nv_bfloat162*)(Clo + (size_t)m*N + n + 2) = lp1;
            } else {
                if (resid){
                    float4 rp = *(const float4*)(resid + (size_t)m*N + n);
                    v0 += rp.x; v1 += rp.y; v2 += rp.z; v3 += rp.w;
                }
                float4 o = make_float4(v0, v1, v2, v3);
                *(float4*)(C + (size_t)m*N + n) = o;
            }
        } else if (n < N){
            #pragma unroll
            for (int j = 0; j < 4; j++){
                int nn = n + j;
                if (nn < N){
                    float v = stg[r*261 + q + j] + bias[nn];
                    if (act == 1) v = 0.5f*v*(1.f + erff(v*0.70710678118654752f));
                    if (Chi){
                        __nv_bfloat16 h0,l0; split2(v,h0,l0);
                        Chi[(size_t)m*N + nn] = h0; Clo[(size_t)m*N + nn] = l0;
                    } else {
                        if (resid) v += resid[(size_t)m*N + nn];
                        C[(size_t)m*N + nn] = v;
                    }
                }
            }
        }
    }
    #undef TGLOAD

#else
    // ---------------- fallback: proven mma.sync path (two 128-wide n halves) ----------
    #define AST 40
    #define T_ELEM (128*AST)
    #define S_ELEM (4*T_ELEM)
    __nv_bfloat16* sm = (__nv_bfloat16*)dyn;
    uint32_t sb = smem_u32(sm);
    int wm = (wid & 1) * 64;
    int wn = (wid >> 1) * 32;
    int nchunks = K >> 5;

    for (int half = 0; half < 2; half++){
        int n0 = nbase + half*128;
        float acc[16][4];
        #pragma unroll
        for (int i = 0; i < 16; i++){
            acc[i][0]=0.f; acc[i][1]=0.f; acc[i][2]=0.f; acc[i][3]=0.f;
        }
        #define PREFETCH(stage, k0) do {                                               \
            uint32_t s0 = sb + (stage)*(S_ELEM*2);                                     \
            _Pragma("unroll")                                                          \
            for (int j = 0; j < 8; j++){                                               \
                int i = tid + j*256;                                                   \
                int tile = i >> 9, r = (i >> 2) & 127, ch = i & 3;                     \
                const __nv_bfloat16* gp;                                               \
                if      (tile == 0) gp = Ahi + (size_t)(m0+r)*lda + (k0) + ch*8;       \
                else if (tile == 1) gp = Alo + (size_t)(m0+r)*lda + (k0) + ch*8;       \
                else if (tile == 2) gp = Bhi + (size_t)(n0+r)*K   + (k0) + ch*8;       \
                else                gp = Blo + (size_t)(n0+r)*K   + (k0) + ch*8;       \
                uint32_t dst = s0 + tile*(T_ELEM*2) + r*(AST*2) + ch*16;               \
                CP_ASYNC16(dst, gp);                                                   \
            }                                                                          \
        } while(0)
        PREFETCH(0, 0);
        CP_COMMIT();
        for (int c = 0; c < nchunks; c++){
            if (c + 1 < nchunks){
                PREFETCH((c+1)&1, (c+1)*32);
                CP_COMMIT();
                CP_WAIT(1);
            } else CP_WAIT(0);
            __syncthreads();
            __nv_bfloat16* st  = sm + (c&1)*S_ELEM;
            __nv_bfloat16* sAh = st;
            __nv_bfloat16* sAl = st + T_ELEM;
            __nv_bfloat16* sBh = st + 2*T_ELEM;
            __nv_bfloat16* sBl = st + 3*T_ELEM;
            #pragma unroll
            for (int ks = 0; ks < 2; ks++){
                int kb = ks * 16 + (lane >> 4) * 8;
                int rr = lane & 15;
                uint32_t ah[4][4], al[4][4], bfr[2][4];
                #pragma unroll
                for (int mi = 0; mi < 4; mi++){
                    uint32_t ad = smem_u32(&sAh[(wm + mi*16 + rr)*AST + kb]);
                    LDSM4(ah[mi][0], ah[mi][1], ah[mi][2], ah[mi][3], ad);
                }
                #pragma unroll
                for (int mi = 0; mi < 4; mi++){
                    uint32_t ad = smem_u32(&sAl[(wm + mi*16 + rr)*AST + kb]);
                    LDSM4(al[mi][0], al[mi][1], al[mi][2], al[mi][3], ad);
                }
                #pragma unroll
                for (int nj = 0; nj < 2; nj++){
                    uint32_t ad = smem_u32(&sBh[(wn + nj*16 + rr)*AST + kb]);
                    LDSM4(bfr[nj][0], bfr[nj][1], bfr[nj][2], bfr[nj][3], ad);
                }
                #pragma unroll
                for (int mi = 0; mi < 4; mi++)
                    #pragma unroll
                    for (int ni = 0; ni < 4; ni++){
                        uint32_t b0 = bfr[ni>>1][(ni&1)];
                        uint32_t b1 = bfr[ni>>1][(ni&1)+2];
                        MMA16816(acc[mi*4+ni], ah[mi], b0, b1);
                        MMA16816(acc[mi*4+ni], al[mi], b0, b1);
                    }
                #pragma unroll
                for (int nj = 0; nj < 2; nj++){
                    uint32_t ad = smem_u32(&sBl[(wn + nj*16 + rr)*AST + kb]);
                    LDSM4(bfr[nj][0], bfr[nj][1], bfr[nj][2], bfr[nj][3], ad);
                }
                #pragma unroll
                for (int mi = 0; mi < 4; mi++)
                    #pragma unroll
                    for (int ni = 0; ni < 4; ni++){
                        uint32_t b0 = bfr[ni>>1][(ni&1)];
                        uint32_t b1 = bfr[ni>>1][(ni&1)+2];
                        MMA16816(acc[mi*4+ni], ah[mi], b0, b1);
                    }
            }
            __syncthreads();
        }
        #pragma unroll
        for (int mi = 0; mi < 4; mi++){
            #pragma unroll
            for (int ni = 0; ni < 4; ni++){
                float* ac = acc[mi*4+ni];
                int n = n0 + wn + ni*8 + (lane & 3)*2;
                if (n + 1 < N){
                    float b0 = bias[n], b1 = bias[n+1];
                    #pragma unroll
                    for (int hf = 0; hf < 2; hf++){
                        int m = m0 + wm + mi*16 + (lane >> 2) + hf*8;
                        float v0 = ac[hf*2]   + b0;
                        float v1 = ac[hf*2+1] + b1;
                        if (act == 1){
                            v0 = 0.5f*v0*(1.f + erff(v0*0.70710678118654752f));
                            v1 = 0.5f*v1*(1.f + erff(v1*0.70710678118654752f));
                        }
                        if (Chi){
                            __nv_bfloat16 h0,l0,h1,l1;
                            split2(v0,h0,l0); split2(v1,h1,l1);
                            __nv_bfloat162 hp, lp;
                            hp.x=h0; hp.y=h1; lp.x=l0; lp.y=l1;
                            *(__nv_bfloat162*)(Chi + (size_t)m*N + n) = hp;
                            *(__nv_bfloat162*)(Clo + (size_t)m*N + n) = lp;
                        } else {
                            if (resid){
                                float2 rp = *(const float2*)(resid + (size_t)m*N + n);
                                v0 += rp.x; v1 += rp.y;
                            }
                            float2 o = make_float2(v0, v1);
                            *(float2*)(C + (size_t)m*N + n) = o;
                        }
                    }
                } else if (n < N){
                    float b0 = bias[n];
                    #pragma unroll
                    for (int hf = 0; hf < 2; hf++){
                        int m = m0 + wm + mi*16 + (lane >> 2) + hf*8;
                        float v0 = ac[hf*2] + b0;
                        if (act == 1) v0 = 0.5f*v0*(1.f + erff(v0*0.70710678118654752f));
                        if (Chi){
                            __nv_bfloat16 h0,l0; split2(v0,h0,l0);
                            Chi[(size_t)m*N + n] = h0;
                            Clo[(size_t)m*N + n] = l0;
                        } else {
                            if (resid) v0 += resid[(size_t)m*N + n];
                            C[(size_t)m*N + n] = v0;
                        }
                    }
                }
            }
        }
        __syncthreads();
        #undef PREFETCH
    }
#endif
}

// ---------------- timestep embedding features ----------------
__global__ void k_tfeat(const float* __restrict__ t, float* __restrict__ out){
    int i = blockIdx.x*blockDim.x + threadIdx.x;
    if (i >= NB*NCD) return;
    int b = i / NCD, j = i % NCD;
    const int half = NCD/2;
    int idx = (j < half) ? j : (j - half);
    float f   = expf(-9.210340371976184f * (float)idx / (float)half);
    float ang = t[b] * f;
    out[i] = (j < half) ? sinf(ang) : cosf(ang);
}

// ---------------- small GEMM (rows = NB only) ----------------
__global__ __launch_bounds__(256) void k_sgemm2(const float* __restrict__ X,
                                                const float* __restrict__ W,
                                                const float* __restrict__ bias,
                                                float* __restrict__ Y,
                                                int K, int N, int act){
    __shared__ float red[2][4][65];
    int lane = threadIdx.x & 63;
    int slice = threadIdx.x >> 6;
    int n = blockIdx.x*64 + lane;
    int kps = K >> 2;
    float a0 = 0.f, a1 = 0.f;
    if (n < N){
        const float* x0 = X;
        const float* x1 = X + K;
        int k0 = slice*kps, k1 = k0 + kps;
        #pragma unroll 4
        for (int k = k0; k < k1; k++){
            float w = W[(size_t)k*N + n];
            a0 += x0[k]*w; a1 += x1[k]*w;
        }
    }
    red[0][slice][lane] = a0;
    red[1][slice][lane] = a1;
    __syncthreads();
    if (threadIdx.x < 128){
        int bb = threadIdx.x >> 6, l = threadIdx.x & 63;
        float s = red[bb][0][l] + red[bb][1][l] + red[bb][2][l] + red[bb][3][l];
        int nn = blockIdx.x*64 + l;
        if (nn < N){
            s += bias[nn];
            if (act == 1) s = s / (1.f + expf(-s));
            Y[(size_t)bb*N + nn] = s;
        }
    }
}

// ---------------- rope tables + apply ----------------
__global__ void k_rope_tab(){
    int i = blockIdx.x*blockDim.x + threadIdx.x;
    if (i >= NT*(NDH/2)) return;
    int t = i >> 5, j = i & 31;
    float freq = (float)pow(10000.0, -(double)(2*j) / (double)NDH);
    float ang  = (float)t * freq;
    g_rc[i] = cosf(ang);
    g_rs[i] = sinf(ang);
}
__global__ void k_rope(float* __restrict__ qkv){
    int i = blockIdx.x*blockDim.x + threadIdx.x;
    int j = i & 31;
    int h = (i >> 5) & 15;
    int c = (i >> 9) & 1;
    int t = (i >> 10) & (NT-1);
    int b = i >> 21;
    size_t base = (((size_t)(b*NT + t)*3 + c)*NH + h) * NDH;
    float x1 = qkv[base + 2*j], x2 = qkv[base + 2*j + 1];
    float cs = g_rc[t*32 + j], sn = g_rs[t*32 + j];
    qkv[base + 2*j]     = x1*cs - x2*sn;
    qkv[base + 2*j + 1] = x1*sn + x2*cs;
}

// ---------------- LayerNorm (+adaLN), split bf16 hi/lo output ----------------
__global__ __launch_bounds__(256) void k_ln(const float* __restrict__ X,
                                            const float* __restrict__ ss,
                                            __nv_bfloat16* __restrict__ Yh,
                                            __nv_bfloat16* __restrict__ Yl){
    int row = blockIdx.x;
    int b = row / NT;
    const float4* x4 = (const float4*)(X + (size_t)row*ND);
    int tid = threadIdx.x;
    float4 v = x4[tid];
    float s = v.x+v.y+v.z+v.w;
    float q = v.x*v.x+v.y*v.y+v.z*v.z+v.w*v.w;
    #pragma unroll
    for (int o=16;o;o>>=1){ s += __shfl_xor_sync(0xffffffffu,s,o); q += __shfl_xor_sync(0xffffffffu,q,o); }
    __shared__ float shs[8], shq[8];
    __shared__ float smean, srstd;
    int w = tid>>5;
    if ((tid&31)==0){ shs[w]=s; shq[w]=q; }
    __syncthreads();
    if (tid==0){
        float S=0.f,Q=0.f;
        #pragma unroll
        for (int k=0;k<8;k++){ S+=shs[k]; Q+=shq[k]; }
        float mean = S*(1.f/ND);
        float var  = Q*(1.f/ND) - mean*mean;
        smean = mean; srstd = rsqrtf(var + LNEPS);
    }
    __syncthreads();
    float mean = smean, r = srstd;
    int n0 = tid*4;
    float o[4];
    o[0]=(v.x-mean)*r; o[1]=(v.y-mean)*r; o[2]=(v.z-mean)*r; o[3]=(v.w-mean)*r;
    if (ss){
        const float* sc = ss + (size_t)b*2*ND;
        const float* sh = sc + ND;
        #pragma unroll
        for (int j=0;j<4;j++) o[j] = o[j]*(1.f+sc[n0+j]) + sh[n0+j];
    }
    __nv_bfloat16 hh[4], ll[4];
    #pragma unroll
    for (int j=0;j<4;j++) split2(o[j], hh[j], ll[j]);
    *(uint2*)(Yh + (size_t)row*ND + n0) = *(uint2*)hh;
    *(uint2*)(Yl + (size_t)row*ND + n0) = *(uint2*)ll;
}

// ---------------- flash-style windowed causal attention (fp32, split bf16 out) --------
__global__ __launch_bounds__(256) void k_attn(const float* __restrict__ qkv,
                                              __nv_bfloat16* __restrict__ Oh,
                                              __nv_bfloat16* __restrict__ Ol){
    extern __shared__ float smf[];
    float* Qs = smf;
    float* KP = smf + 64*65;
    float* Vs = smf + 2*64*65;
    int qt = blockIdx.x, h = blockIdx.y, b = blockIdx.z;
    int tid = threadIdx.x, ty = tid>>4, tx = tid&15;
    int q0 = qt*64;
    const float scale = 0.125f;

    #pragma unroll
    for (int rep=0;rep<4;rep++){
        int f = tid + rep*256;
        int r = f>>4, c4 = (f&15)*4;
        size_t g = (((size_t)(b*NT + q0 + r)*3 + 0)*NH + h)*NDH + c4;
        float4 v = *(const float4*)(qkv + g);
        Qs[r*65 + c4  ] = v.x*scale;
        Qs[r*65 + c4+1] = v.y*scale;
        Qs[r*65 + c4+2] = v.z*scale;
        Qs[r*65 + c4+3] = v.w*scale;
    }
    __syncthreads();

    float Oa[4][4];
    float mo[4], lo[4];
    #pragma unroll
    for (int a=0;a<4;a++){
        mo[a] = -1e30f; lo[a] = 0.f;
        #pragma unroll
        for (int c=0;c<4;c++) Oa[a][c]=0.f;
    }

    int ktiles = min(8, qt+1);
    for (int jt=0; jt<ktiles; jt++){
        int j0 = jt*64;
        #pragma unroll
        for (int rep=0;rep<4;rep++){
            int f = tid + rep*256;
            int r = f>>4, c4 = (f&15)*4;
            int tok = NT - NWIN + j0 + r;
            size_t gk = (((size_t)(b*NT + tok)*3 + 1)*NH + h)*NDH + c4;
            float4 kv = *(const float4*)(qkv + gk);
            float4 vv = *(const float4*)(qkv + gk + (size_t)NH*NDH);
            KP[r*65+c4  ]=kv.x; KP[r*65+c4+1]=kv.y;
            KP[r*65+c4+2]=kv.z; KP[r*65+c4+3]=kv.w;
            *(float4*)(Vs + r*64 + c4) = vv;
        }
        __syncthreads();

        float S[4][4];
        #pragma unroll
        for (int a=0;a<4;a++)
            #pragma unroll
            for (int bb=0;bb<4;bb++) S[a][bb]=0.f;
        for (int d=0; d<64; d++){
            float qa[4], kb[4];
            #pragma unroll
            for (int a=0;a<4;a++)  qa[a] = Qs[(ty+16*a)*65 + d];
            #pragma unroll
            for (int bb=0;bb<4;bb++) kb[bb] = KP[(tx+16*bb)*65 + d];
            #pragma unroll
            for (int a=0;a<4;a++)
                #pragma unroll
                for (int bb=0;bb<4;bb++) S[a][bb] += qa[a]*kb[bb];
        }
        if (jt == qt){
            #pragma unroll
            for (int a=0;a<4;a++)
                #pragma unroll
                for (int bb=0;bb<4;bb++)
                    if (tx+16*bb > ty+16*a) S[a][bb] = -1e30f;
        }

        float P[4][4];
        #pragma unroll
        for (int a=0;a<4;a++){
            float mx = fmaxf(fmaxf(S[a][0],S[a][1]), fmaxf(S[a][2],S[a][3]));
            mx = fmaxf(mx, __shfl_xor_sync(0xffffffffu, mx, 8));
            mx = fmaxf(mx, __shfl_xor_sync(0xffffffffu, mx, 4));
            mx = fmaxf(mx, __shfl_xor_sync(0xffffffffu, mx, 2));
            mx = fmaxf(mx, __shfl_xor_sync(0xffffffffu, mx, 1));
            float mn = fmaxf(mo[a], mx);
            float ls = 0.f;
            #pragma unroll
            for (int bb=0;bb<4;bb++){ P[a][bb] = expf(S[a][bb]-mn); ls += P[a][bb]; }
            ls += __shfl_xor_sync(0xffffffffu, ls, 8);
            ls += __shfl_xor_sync(0xffffffffu, ls, 4);
            ls += __shfl_xor_sync(0xffffffffu, ls, 2);
            ls += __shfl_xor_sync(0xffffffffu, ls, 1);
            float alpha = expf(mo[a]-mn);
            lo[a] = lo[a]*alpha + ls;
            mo[a] = mn;
            #pragma unroll
            for (int c=0;c<4;c++) Oa[a][c] *= alpha;
        }
        __syncthreads();
        #pragma unroll
        for (int a=0;a<4;a++)
            #pragma unroll
            for (int bb=0;bb<4;bb++)
                KP[(ty+16*a)*65 + tx+16*bb] = P[a][bb];
        __syncthreads();
        for (int jj=0;jj<64;jj++){
            float pa[4], vc[4];
            #pragma unroll
            for (int a=0;a<4;a++) pa[a] = KP[(ty+16*a)*65 + jj];
            #pragma unroll
            for (int c=0;c<4;c++) vc[c] = Vs[jj*64 + tx+16*c];
            #pragma unroll
            for (int a=0;a<4;a++)
                #pragma unroll
                for (int c=0;c<4;c++) Oa[a][c] += pa[a]*vc[c];
        }
        __syncthreads();
    }
    #pragma unroll
    for (int a=0;a<4;a++){
        int qq = q0 + ty + 16*a;
        float inv = 1.f/lo[a];
        #pragma unroll
        for (int c=0;c<4;c++){
            float v = Oa[a][c]*inv;
            __nv_bfloat16 hh, ll; split2(v, hh, ll);
            size_t idx = (((size_t)(b*NT+qq))*NH + h)*NDH + tx + 16*c;
            Oh[idx] = hh; Ol[idx] = ll;
        }
    }
}

// ---------------- orchestration ----------------
extern "C" void kernel_launch(void* const* d_in, const int* in_sizes, int n_in,
                              void* d_out, int out_size){
    (void)in_sizes; (void)n_in; (void)out_size;
    const float* x      = (const float*)d_in[0];
    const float* t      = (const float*)d_in[1];
    const float* W_in   = (const float*)d_in[2];
    const float* b_in   = (const float*)d_in[3];
    const float* Wt1    = (const float*)d_in[4];
    const float* bt1    = (const float*)d_in[5];
    const float* Wt2    = (const float*)d_in[6];
    const float* bt2    = (const float*)d_in[7];
    const float* Wcm    = (const float*)d_in[8];
    const float* bcm    = (const float*)d_in[9];
    const float* ada1_W = (const float*)d_in[10];
    const float* ada1_b = (const float*)d_in[11];
    const float* qkv_W  = (const float*)d_in[12];
    const float* qkv_b  = (const float*)d_in[13];
    const float* attno_W= (const float*)d_in[14];
    const float* attno_b= (const float*)d_in[15];
    const float* ada2_W = (const float*)d_in[16];
    const float* ada2_b = (const float*)d_in[17];
    const float* mlp_W1 = (const float*)d_in[18];
    const float* mlp_b1 = (const float*)d_in[19];
    const float* mlp_W2 = (const float*)d_in[20];
    const float* mlp_b2 = (const float*)d_in[21];
    const float* W_out  = (const float*)d_in[22];
    const float* b_out  = (const float*)d_in[23];

    float *p_h,*p_qkv,*p_ta,*p_tb,*p_cond,*p_ss;
    cudaGetSymbolAddress((void**)&p_h,    g_h);
    cudaGetSymbolAddress((void**)&p_qkv,  g_qkv);
    cudaGetSymbolAddress((void**)&p_ta,   g_ta);
    cudaGetSymbolAddress((void**)&p_tb,   g_tb);
    cudaGetSymbolAddress((void**)&p_cond, g_cond);
    cudaGetSymbolAddress((void**)&p_ss,   g_ss);

    __nv_bfloat16 *p_xh,*p_xl,*p_hnh,*p_hnl,*p_ath,*p_atl,*p_ffh,*p_ffl;
    cudaGetSymbolAddress((void**)&p_xh,  g_xh);
    cudaGetSymbolAddress((void**)&p_xl,  g_xl);
    cudaGetSymbolAddress((void**)&p_hnh, g_hn_h);
    cudaGetSymbolAddress((void**)&p_hnl, g_hn_l);
    cudaGetSymbolAddress((void**)&p_ath, g_at_h);
    cudaGetSymbolAddress((void**)&p_atl, g_at_l);
    cudaGetSymbolAddress((void**)&p_ffh, g_ff_h);
    cudaGetSymbolAddress((void**)&p_ffl, g_ff_l);

    __nv_bfloat16 *w_in_h,*w_in_l,*w_qkv_h,*w_qkv_l,*w_ao_h,*w_ao_l;
    __nv_bfloat16 *w_m1_h,*w_m1_l,*w_m2_h,*w_m2_l,*w_out_h,*w_out_l;
    cudaGetSymbolAddress((void**)&w_in_h,  c_in_hi);
    cudaGetSymbolAddress((void**)&w_in_l,  c_in_lo);
    cudaGetSymbolAddress((void**)&w_qkv_h, c_qkv_hi);
    cudaGetSymbolAddress((void**)&w_qkv_l, c_qkv_lo);
    cudaGetSymbolAddress((void**)&w_ao_h,  c_ao_hi);
    cudaGetSymbolAddress((void**)&w_ao_l,  c_ao_lo);
    cudaGetSymbolAddress((void**)&w_m1_h,  c_m1_hi);
    cudaGetSymbolAddress((void**)&w_m1_l,  c_m1_lo);
    cudaGetSymbolAddress((void**)&w_m2_h,  c_m2_hi);
    cudaGetSymbolAddress((void**)&w_m2_l,  c_m2_lo);
    cudaGetSymbolAddress((void**)&w_out_h, c_out_hi);
    cudaGetSymbolAddress((void**)&w_out_l, c_out_lo);

    cudaFuncSetAttribute(k_attn,  cudaFuncAttributeMaxDynamicSharedMemorySize, 49664);
    cudaFuncSetAttribute(k_tgemm, cudaFuncAttributeMaxDynamicSharedMemorySize, TG_SMEM);

    const int M = NB*NT;
    dim3 wblk(32, 8);

    // ---- weight conversion ----
    k_wconv<<<dim3(ND/32, 128/32), wblk>>>(W_in,  w_in_h,  w_in_l,  NMEL, ND, 128);
    k_wconv<<<dim3(256/32, ND/32), wblk>>>(W_out, w_out_h, w_out_l, ND, NMEL, ND);
    for (int l = 0; l < NLAYER; l++){
        k_wconv<<<dim3(3*ND/32, ND/32), wblk>>>(qkv_W  + (size_t)l*ND*3*ND, w_qkv_h + (size_t)l*3*ND*ND, w_qkv_l + (size_t)l*3*ND*ND, ND, 3*ND, ND);
        k_wconv<<<dim3(ND/32,   ND/32), wblk>>>(attno_W+ (size_t)l*ND*ND,   w_ao_h  + (size_t)l*ND*ND,   w_ao_l  + (size_t)l*ND*ND,   ND, ND, ND);
        k_wconv<<<dim3(NFF/32,  ND/32), wblk>>>(mlp_W1 + (size_t)l*ND*NFF,  w_m1_h  + (size_t)l*NFF*ND,  w_m1_l  + (size_t)l*NFF*ND,  ND, NFF, ND);
        k_wconv<<<dim3(ND/32,  NFF/32), wblk>>>(mlp_W2 + (size_t)l*NFF*ND,  w_m2_h  + (size_t)l*ND*NFF,  w_m2_l  + (size_t)l*ND*NFF,  NFF, ND, NFF);
    }

    // ---- timestep conditioning ----
    k_tfeat<<<(NB*NCD+255)/256,256>>>(t, p_ta);
    k_sgemm2<<<NCD/64,256>>>(p_ta, Wt1, bt1, p_tb, NCD, NCD, 1);
    k_sgemm2<<<NCD/64,256>>>(p_tb, Wt2, bt2, p_ta, NCD, NCD, 0);
    k_sgemm2<<<ND/64, 256>>>(p_ta, Wcm, bcm, p_cond, NCD, ND, 1);
    k_rope_tab<<<(NT*32+255)/256,256>>>();

    // ---- input projection (padded K = 128) ----
    k_split<<<(M*128)/256, 256>>>(x, p_xh, p_xl);
    k_tgemm<<<dim3(32, 4), 256, TG_SMEM>>>(p_xh, p_xl, 128, w_in_h, w_in_l,
                                           b_in, nullptr, p_h, nullptr, nullptr,
                                           ND, 128, 0);

    for (int l = 0; l < NLAYER; l++){
        k_sgemm2<<<2*ND/64,256>>>(p_cond, ada1_W + (size_t)l*ND*2*ND,
                                  ada1_b + (size_t)l*2*ND, p_ss, ND, 2*ND, 0);
        k_ln<<<M,256>>>(p_h, p_ss, p_hnh, p_hnl);
        k_tgemm<<<dim3(32, 12), 256, TG_SMEM>>>(p_hnh, p_hnl, ND,
                                                w_qkv_h + (size_t)l*3*ND*ND,
                                                w_qkv_l + (size_t)l*3*ND*ND,
                                                qkv_b + (size_t)l*3*ND, nullptr,
                                                p_qkv, nullptr, nullptr,
                                                3*ND, ND, 0);
        k_rope<<<(1<<22)/256,256>>>(p_qkv);
        k_attn<<<dim3(NT/64, NH, NB), 256, 49664>>>(p_qkv, p_ath, p_atl);
        k_tgemm<<<dim3(32, 4), 256, TG_SMEM>>>(p_ath, p_atl, ND,
                                               w_ao_h + (size_t)l*ND*ND,
                                               w_ao_l + (size_t)l*ND*ND,
                                               attno_b + (size_t)l*ND, p_h,
                                               p_h, nullptr, nullptr,
                                               ND, ND, 0);
        k_sgemm2<<<2*ND/64,256>>>(p_cond, ada2_W + (size_t)l*ND*2*ND,
                                  ada2_b + (size_t)l*2*ND, p_ss, ND, 2*ND, 0);
        k_ln<<<M,256>>>(p_h, p_ss, p_hnh, p_hnl);
        k_tgemm<<<dim3(32, 16), 256, TG_SMEM>>>(p_hnh, p_hnl, ND,
                                                w_m1_h + (size_t)l*NFF*ND,
                                                w_m1_l + (size_t)l*NFF*ND,
                                                mlp_b1 + (size_t)l*NFF, nullptr,
                                                nullptr, p_ffh, p_ffl,
                                                NFF, ND, 1);
        k_tgemm<<<dim3(32, 4), 256, TG_SMEM>>>(p_ffh, p_ffl, NFF,
                                               w_m2_h + (size_t)l*ND*NFF,
                                               w_m2_l + (size_t)l*ND*NFF,
                                               mlp_b2 + (size_t)l*ND, p_h,
                                               p_h, nullptr, nullptr,
                                               ND, NFF, 0);
    }

    k_ln<<<M,256>>>(p_h, nullptr, p_hnh, p_hnl);
    k_tgemm<<<dim3(32, 1), 256, TG_SMEM>>>(p_hnh, p_hnl, ND, w_out_h, w_out_l,
                                           b_out, nullptr, (float*)d_out,
                                           nullptr, nullptr, NMEL, ND, 0);
}